// round 15
// baseline (speedup 1.0000x reference)
#include <cuda_runtime.h>
#include <cstddef>

// Problem constants
#define B_  64
#define L_  2048
#define C_  20
#define H1_ 384
#define H2_ 16
#define F_  20

// Output layout (flattened tuple, reference order):
// x_mid (B,L,F) | x_out (B,L,F) | h1f (B,H1) | h2f (B,H2) | h3f (B,F)
#define XMID_OFF 0
#define XOUT_OFF (B_*L_*F_)
#define H1F_OFF  (2*B_*L_*F_)
#define H2F_OFF  (H1F_OFF + B_*H1_)
#define H3F_OFF  (H2F_OFF + B_*H2_)

// Scratch (device globals: allocation-free rule)
__device__ float g_h1[B_*H1_];
__device__ float g_y1[(size_t)B_*L_*H1_];        // 201 MB
__device__ float g_xp[(size_t)B_*L_*48];         // 25 MB (gru2 input proj)
__device__ unsigned g_bar_cnt[8];                // fallback barrier
__device__ unsigned g_bar_gen[8];                // monotonic across launches

// GRU1 partition: 16 row-groups x 8 batch-groups = 128 CTAs.
// Each CTA: 24 hidden units (72 gate rows, SMEM-resident) x 8 batches.
// One batch group = one 16-CTA cluster (HW barrier) or software barrier.
// 512 threads = 16 warps = 8 rgrp x 2 khalf. Warp tile: 9 rows x 8 b x 192 k.
// Lane = (ko 0..7, bl 0..3): 9 rows x 2 batches x 24 k per lane, f32x2 FMA.
#define NBLK1 128
#define CLUS_ 16
#define UPC_  24     // units per CTA
#define RPC_  72     // gate rows per CTA (3*UPC)
#define BPC_  8      // batches per CTA
// SMEM strides (floats): k stored in 4 chunks of 96 (+4 pad)
#define SK_   100
#define SB_   420
#define WROW_ 420

__device__ __forceinline__ unsigned long long fma2_(
    unsigned long long a, unsigned long long b, unsigned long long c)
{
    unsigned long long d;
    asm("fma.rn.f32x2 %0, %1, %2, %3;" : "=l"(d) : "l"(a), "l"(b), "l"(c));
    return d;
}

// ---------------------------------------------------------------------------
// Kernel 1: GRU1 (C=20 -> H1=384), persistent.
// USE_CLUSTER: per-batch-group sync via barrier.cluster (release/acquire).
// else: software grid barrier over the 16 CTAs of the batch group.
// ---------------------------------------------------------------------------
template<bool USE_CLUSTER>
__global__ __launch_bounds__(512, 1) void gru1_t(
    const float* __restrict__ x, const float* __restrict__ h1_in,
    const float* __restrict__ Wih1, const float* __restrict__ Whh1,
    const float* __restrict__ bih1, const float* __restrict__ bhh1,
    float* __restrict__ out_h1f)
{
    extern __shared__ float sm[];
    float* h_s  = sm;                       // BPC*SB   = 3360
    float* Wh_s = h_s  + BPC_*SB_;          // RPC*WROW = 30240
    float* xs   = Wh_s + RPC_*WROW_;        // BPC*20   = 160
    float* Wi_s = xs   + BPC_*C_;           // RPC*20   = 1440
    float* bi_s = Wi_s + RPC_*C_;           // 72
    float* bh_s = bi_s + RPC_;              // 72
    float* red  = bh_s + RPC_;              // 16*72 = 1152

    const int tid  = threadIdx.x;
    const int lane = tid & 31;
    const int w    = tid >> 5;                 // 0..15
    const int rg   = blockIdx.x & (CLUS_-1);   // row group / cluster rank
    const int bg   = blockIdx.x >> 4;          // batch group 0..7
    const int u0   = rg * UPC_;                // first global hidden unit
    const int b0c  = bg * BPC_;                // first global batch

    const int rgrp  = w >> 1;                  // 0..7 -> units rgrp*3..+2
    const int khalf = w & 1;                   // 0..1 -> k 0..191 / 192..383
    const int ko    = lane >> 2;               // k octet within half (24 k)
    const int bl    = lane & 3;                // batch pair base (bl, bl+4)

    // ---- load recurrent weights into SMEM (chunked-k layout) ----
    for (int i = tid; i < RPC_*H1_; i += 512) {
        int lr = i / H1_, k = i % H1_;
        int g = lr / UPC_, ul = lr % UPC_;
        Wh_s[lr*WROW_ + (k/96)*SK_ + (k%96)] =
            Whh1[(size_t)(g*H1_ + u0 + ul)*H1_ + k];
    }
    for (int i = tid; i < RPC_*C_; i += 512) {
        int lr = i / C_, c = i % C_;
        int g = lr / UPC_, ul = lr % UPC_;
        Wi_s[i] = Wih1[(g*H1_ + u0 + ul)*C_ + c];
    }
    if (tid < RPC_) {
        int g = tid / UPC_, ul = tid % UPC_;
        bi_s[tid] = bih1[g*H1_ + u0 + ul];
        bh_s[tid] = bhh1[g*H1_ + u0 + ul];
    }

    // fallback-barrier generation base
    unsigned base = 0;
    if (!USE_CLUSTER) base = *(volatile unsigned*)&g_bar_gen[bg];

    // per-lane k base: global k = khalf*192 + ko*24 + [0..23]
    const int c0  = khalf*2 + (ko >> 2);       // 96-chunk index
    const int off = (ko & 3) * 24;
    const float* hb0 = h_s  + bl*SB_       + c0*SK_ + off;
    const float* hb1 = h_s  + (bl+4)*SB_   + c0*SK_ + off;
    const float* wb  = Wh_s + (rgrp*3)*WROW_ + c0*SK_ + off;

    // epilogue identity (t-invariant): even warps, 24 lanes = 3 units x 8 b
    const bool epi = (khalf == 0) && (lane < 24);
    const int  eu   = lane >> 3;               // 0..2
    const int  ebl  = lane & 7;
    const int  eb   = b0c + ebl;               // global batch
    const int  eul  = rgrp*3 + eu;             // local unit 0..23
    const int  eug  = u0 + eul;                // global hidden unit
    float hn_prev = 0.f;

    for (int t = 0; t < L_; t++) {
        // ---- deferred y1 store from previous step (overlaps h load) ----
        if (t > 0 && epi)
            g_y1[((size_t)eb*L_ + (t-1))*H1_ + eug] = hn_prev;

        // ---- load h state for our 8 batches (L2, bypass L1) ----
        {
            const float4* s4 = (t == 0)
                ? (const float4*)(h1_in + b0c*H1_)
                : (const float4*)(g_h1  + b0c*H1_);
            #pragma unroll 1
            for (int i4 = tid; i4 < BPC_*(H1_/4); i4 += 512) {
                int b = i4 / 96, k4 = i4 % 96;
                float4 v = (t == 0) ? __ldg(s4 + i4) : __ldcg(s4 + i4);
                *((float4*)h_s + (size_t)b*(SB_/4) + (k4/24)*(SK_/4) + (k4%24)) = v;
            }
        }
        // ---- x_t for our batches (8 x 20) ----
        if (tid < BPC_*5) {
            int b = tid / 5, c4 = tid % 5;
            ((float4*)(xs + b*C_))[c4] =
                __ldcg((const float4*)(x + ((size_t)(b0c + b)*L_ + t)*C_) + c4);
        }
        __syncthreads();

        // ---- recurrent GEMM: 9 rows x 2 batches x 24 k per lane ----
        unsigned long long acc[18];
        #pragma unroll
        for (int r = 0; r < 18; r++) acc[r] = 0ull;

        #pragma unroll
        for (int j = 0; j < 6; j++) {
            const ulonglong2 ha = *(const ulonglong2*)(hb0 + 4*j);
            const ulonglong2 hc = *(const ulonglong2*)(hb1 + 4*j);
            #pragma unroll
            for (int g = 0; g < 3; g++) {
                #pragma unroll
                for (int u = 0; u < 3; u++) {
                    const ulonglong2 w2 =
                        *(const ulonglong2*)(wb + (g*UPC_ + u)*WROW_ + 4*j);
                    const int r = g*3 + u;
                    acc[r*2]   = fma2_(w2.x, ha.x, acc[r*2]);
                    acc[r*2]   = fma2_(w2.y, ha.y, acc[r*2]);
                    acc[r*2+1] = fma2_(w2.x, hc.x, acc[r*2+1]);
                    acc[r*2+1] = fma2_(w2.y, hc.y, acc[r*2+1]);
                }
            }
        }
        // unpack f32x2 partials, reduce over ko (lane bits 2..4)
        float s[18];
        #pragma unroll
        for (int r = 0; r < 18; r++) {
            float lo, hi;
            asm("mov.b64 {%0,%1}, %2;" : "=f"(lo), "=f"(hi) : "l"(acc[r]));
            s[r] = lo + hi;
        }
        #pragma unroll
        for (int r = 0; r < 18; r++) {
            s[r] += __shfl_xor_sync(0xffffffffu, s[r], 4);
            s[r] += __shfl_xor_sync(0xffffffffu, s[r], 8);
            s[r] += __shfl_xor_sync(0xffffffffu, s[r], 16);
        }
        if (ko == 0) {
            #pragma unroll
            for (int r = 0; r < 9; r++) {
                red[w*72 + r*8 + bl]     = s[r*2];
                red[w*72 + r*8 + bl + 4] = s[r*2+1];
            }
        }
        __syncthreads();   // cross-warp (khalf) combine

        // ---- epilogue: even warps, 24 lanes = 3 units x 8 batches ----
        if (epi) {
            float xr = bi_s[eul], xz = bi_s[UPC_+eul], xn = bi_s[2*UPC_+eul];
            #pragma unroll
            for (int c = 0; c < C_; c++) {
                float xv = xs[ebl*C_ + c];
                xr = fmaf(Wi_s[eul*C_ + c],            xv, xr);
                xz = fmaf(Wi_s[(UPC_+eul)*C_ + c],     xv, xz);
                xn = fmaf(Wi_s[(2*UPC_+eul)*C_ + c],   xv, xn);
            }
            const int w0 = rgrp*2, w1 = rgrp*2 + 1;
            float ghr = red[w0*72 + (eu  )*8 + ebl] + red[w1*72 + (eu  )*8 + ebl] + bh_s[eul];
            float ghz = red[w0*72 + (3+eu)*8 + ebl] + red[w1*72 + (3+eu)*8 + ebl] + bh_s[UPC_+eul];
            float ghn = red[w0*72 + (6+eu)*8 + ebl] + red[w1*72 + (6+eu)*8 + ebl] + bh_s[2*UPC_+eul];
            float rgt = 1.f / (1.f + __expf(-(xr + ghr)));
            float zgt = 1.f / (1.f + __expf(-(xz + ghz)));
            float ngt = tanhf(xn + rgt * ghn);
            float hold = h_s[ebl*SB_ + (eug/96)*SK_ + (eug%96)];
            float hn = (1.f - zgt) * ngt + zgt * hold;
            __stcg(&g_h1[eb*H1_ + eug], hn);   // visible before barrier release
            hn_prev = hn;                      // y1 store deferred to next step
            if (t == L_-1) {
                out_h1f[eb*H1_ + eug] = hn;
                g_y1[((size_t)eb*L_ + t)*H1_ + eug] = hn;
            }
        }

        // ---- per-batch-group barrier ----
        if constexpr (USE_CLUSTER) {
            asm volatile("barrier.cluster.arrive.aligned;" ::: "memory");
            asm volatile("barrier.cluster.wait.aligned;"   ::: "memory");
        } else {
            __threadfence();
            __syncthreads();
            if (tid == 0) {
                unsigned a = atomicAdd(&g_bar_cnt[bg], 1u);
                if (a == CLUS_ - 1) {
                    g_bar_cnt[bg] = 0;
                    __threadfence();
                    *(volatile unsigned*)&g_bar_gen[bg] = base + (unsigned)(t + 1);
                } else {
                    while (*(volatile unsigned*)&g_bar_gen[bg] - base < (unsigned)(t + 1))
                        __nanosleep(16);
                }
            }
            __syncthreads();
        }
    }
}

// ---------------------------------------------------------------------------
// Kernel 2a: gru2 input projection xp = y1 @ Wih2^T + bih2  (time-parallel).
// ---------------------------------------------------------------------------
__global__ __launch_bounds__(256) void gru2a_kernel(
    const float* __restrict__ Wih2, const float* __restrict__ bih2)
{
    extern __shared__ float sm[];
    float* W2s = sm;                 // 48*384 = 18432
    float* bis = W2s + 48*H1_;       // 48
    float* xps = bis + 48;           // 8 warps * 4 rows * 48 = 1536

    const int tid = threadIdx.x, lane = tid & 31, w = tid >> 5;

    for (int i = tid; i < 48*H1_; i += 256) W2s[i] = Wih2[i];
    if (tid < 48) bis[tid] = bih2[tid];
    __syncthreads();

    const int nquad = (B_*L_) / 4;                 // 32768
    const int gw    = blockIdx.x*8 + w;            // global warp id
    const int nw    = gridDim.x*8;

    for (int q = gw; q < nquad; q += nw) {
        const int row0 = q * 4;
        float4 y[4][3];
        #pragma unroll
        for (int r = 0; r < 4; r++) {
            const float4* yr = (const float4*)(g_y1 + (size_t)(row0 + r)*H1_);
            y[r][0] = __ldg(yr + lane);
            y[r][1] = __ldg(yr + 32 + lane);
            y[r][2] = __ldg(yr + 64 + lane);
        }
        for (int g = 0; g < 48; g++) {
            const float* wr = W2s + g*H1_;
            const float4 w0 = *(const float4*)(wr + 4*lane);
            const float4 w1 = *(const float4*)(wr + 128 + 4*lane);
            const float4 w2 = *(const float4*)(wr + 256 + 4*lane);
            #pragma unroll
            for (int r = 0; r < 4; r++) {
                float s = w0.x*y[r][0].x + w0.y*y[r][0].y
                        + w0.z*y[r][0].z + w0.w*y[r][0].w;
                s = fmaf(w1.x, y[r][1].x, s); s = fmaf(w1.y, y[r][1].y, s);
                s = fmaf(w1.z, y[r][1].z, s); s = fmaf(w1.w, y[r][1].w, s);
                s = fmaf(w2.x, y[r][2].x, s); s = fmaf(w2.y, y[r][2].y, s);
                s = fmaf(w2.z, y[r][2].z, s); s = fmaf(w2.w, y[r][2].w, s);
                #pragma unroll
                for (int d = 16; d > 0; d >>= 1)
                    s += __shfl_xor_sync(0xffffffffu, s, d);
                if (lane == (g & 31)) xps[(w*4 + r)*48 + g] = s + bis[g];
            }
        }
        __syncwarp();
        #pragma unroll
        for (int r = 0; r < 4; r++)
            if (lane < 12)
                ((float4*)&g_xp[(size_t)(row0 + r)*48])[lane] =
                    ((float4*)&xps[(w*4 + r)*48])[lane];
        __syncwarp();
    }
}

// ---------------------------------------------------------------------------
// Kernel 2b: gru2 recurrence (H2=16) + ReLU + dual-FC -> x_mid.
// One warp per batch; h in registers; shuffle broadcasts; xp ring prefetch.
// ---------------------------------------------------------------------------
__global__ __launch_bounds__(32) void gru2b_kernel(
    const float* __restrict__ h2_in,
    const float* __restrict__ Whh2, const float* __restrict__ bhh2,
    const float* __restrict__ Wfc,  const float* __restrict__ bfc,
    float* __restrict__ out)
{
    __shared__ float Wh[48*16], Wf[20*16], bh[48], bf[20];
    __shared__ __align__(16) float ring[4][48];

    const int lane = threadIdx.x;
    const int b = blockIdx.x;
    const int r0 = lane & 15;
    const int fr = (lane < 20) ? lane : 0;

    for (int i = lane; i < 48*16; i += 32) Wh[i] = Whh2[i];
    for (int i = lane; i < 20*16; i += 32) Wf[i] = Wfc[i];
    for (int i = lane; i < 48;    i += 32) bh[i] = bhh2[i];
    if (lane < 20) bf[lane] = bfc[lane];

    float h = (lane < 16) ? h2_in[b*H2_ + lane] : 0.f;

    const float* xpb = g_xp + (size_t)b*L_*48;
    if (lane < 24) {   // prime rows 0,1
        int r = lane / 12, c = lane % 12;
        ((float4*)ring[r])[c] = __ldg((const float4*)(xpb + r*48) + c);
    }
    __syncwarp();

    for (int t = 0; t < L_; t++) {
        float4 pf;
        const bool dp = (lane < 12) && (t + 2 < L_);
        if (dp) pf = __ldg((const float4*)(xpb + (size_t)(t + 2)*48) + lane);

        const float* cur = ring[t & 3];

        float ghr = bh[r0], ghz = bh[16 + r0], ghn = bh[32 + r0];
        #pragma unroll
        for (int k = 0; k < 16; k++) {
            float hv = __shfl_sync(0xffffffffu, h, k);
            ghr = fmaf(Wh[r0*16 + k],        hv, ghr);
            ghz = fmaf(Wh[(16+r0)*16 + k],   hv, ghz);
            ghn = fmaf(Wh[(32+r0)*16 + k],   hv, ghn);
        }
        float rg = 1.f / (1.f + __expf(-(cur[r0]      + ghr)));
        float zg = 1.f / (1.f + __expf(-(cur[16 + r0] + ghz)));
        float ng = tanhf(cur[32 + r0] + rg * ghn);
        float hn = (1.f - zg) * ng + zg * h;
        if (lane < 16) h = hn;
        float y2 = fmaxf(hn, 0.f);

        float a = bf[fr];
        #pragma unroll
        for (int k = 0; k < 16; k++) {
            float yv = __shfl_sync(0xffffffffu, y2, k);
            a = fmaf(Wf[fr*16 + k], yv, a);
        }
        if (lane < 20)
            out[XMID_OFF + ((size_t)b*L_ + t)*F_ + lane] = 2.f * tanhf(a);

        if (dp) ((float4*)ring[(t + 2) & 3])[lane] = pf;
        __syncwarp();
    }
    if (lane < 16) out[H2F_OFF + b*H2_ + lane] = h;
}

// ---------------------------------------------------------------------------
// Kernel 3: GRU3 (F=20 -> F=20) on time-reversed x_mid, x_out = tanh(y3).
// One warp per batch element.
// ---------------------------------------------------------------------------
__global__ __launch_bounds__(32) void gru3_kernel(
    const float* __restrict__ h3_in,
    const float* __restrict__ Wih3, const float* __restrict__ Whh3,
    const float* __restrict__ bih3, const float* __restrict__ bhh3,
    float* __restrict__ out)
{
    __shared__ float Wi[60*20], Wh[60*20];
    __shared__ float bi[60], bh[60], as_[60], gs_[60], h3s[20];
    __shared__ __align__(16) float ins[2][20];

    const int lane = threadIdx.x;
    const int b = blockIdx.x;

    for (int i = lane; i < 60*20; i += 32) { Wi[i] = Wih3[i]; Wh[i] = Whh3[i]; }
    for (int i = lane; i < 60;    i += 32) { bi[i] = bih3[i]; bh[i] = bhh3[i]; }
    if (lane < 20) h3s[lane] = h3_in[b*F_ + lane];

    const float* xmid = out + XMID_OFF + (size_t)b*L_*F_;
    if (lane < 5)
        ((float4*)ins[0])[lane] = *((const float4*)(xmid + (size_t)(L_-1)*F_) + lane);
    __syncwarp();

    for (int t = 0; t < L_; t++) {
        float* in = ins[t & 1];
        float4 pf;
        bool dopf = (lane < 5) && (t + 1 < L_);
        if (dopf)
            pf = *((const float4*)(xmid + (size_t)(L_-2-t)*F_) + lane);

        const int r1 = lane + 32;
        const bool has1 = (r1 < 60);
        float a0 = bi[lane], g0 = bh[lane], a1 = 0.f, g1 = 0.f;
        if (has1) { a1 = bi[r1]; g1 = bh[r1]; }
        #pragma unroll
        for (int k = 0; k < 20; k++) {
            float iv = in[k], hv = h3s[k];
            a0 = fmaf(Wi[lane*20 + k], iv, a0);
            g0 = fmaf(Wh[lane*20 + k], hv, g0);
            if (has1) {
                a1 = fmaf(Wi[r1*20 + k], iv, a1);
                g1 = fmaf(Wh[r1*20 + k], hv, g1);
            }
        }
        as_[lane] = a0; gs_[lane] = g0;
        if (has1) { as_[r1] = a1; gs_[r1] = g1; }
        __syncwarp();

        float hn = 0.f;
        if (lane < 20) {
            float rg = 1.f / (1.f + __expf(-(as_[lane] + gs_[lane])));
            float zg = 1.f / (1.f + __expf(-(as_[20+lane] + gs_[20+lane])));
            float ng = tanhf(as_[40+lane] + rg * gs_[40+lane]);
            hn = (1.f - zg) * ng + zg * h3s[lane];
        }
        __syncwarp();
        if (lane < 20) {
            h3s[lane] = hn;
            out[XOUT_OFF + ((size_t)b*L_ + t)*F_ + lane] = tanhf(hn);
        }
        if (dopf) ((float4*)ins[(t + 1) & 1])[lane] = pf;
        __syncwarp();
    }
    if (lane < 20) out[H3F_OFF + b*F_ + lane] = h3s[lane];
}

// ---------------------------------------------------------------------------
extern "C" void kernel_launch(void* const* d_in, const int* in_sizes, int n_in,
                              void* d_out, int out_size)
{
    const float* x    = (const float*)d_in[0];
    const float* h1   = (const float*)d_in[1];
    const float* h2   = (const float*)d_in[2];
    const float* h3   = (const float*)d_in[3];
    const float* Wih1 = (const float*)d_in[4];
    const float* Whh1 = (const float*)d_in[5];
    const float* bih1 = (const float*)d_in[6];
    const float* bhh1 = (const float*)d_in[7];
    const float* Wih2 = (const float*)d_in[8];
    const float* Whh2 = (const float*)d_in[9];
    const float* bih2 = (const float*)d_in[10];
    const float* bhh2 = (const float*)d_in[11];
    const float* Wih3 = (const float*)d_in[12];
    const float* Whh3 = (const float*)d_in[13];
    const float* bih3 = (const float*)d_in[14];
    const float* bhh3 = (const float*)d_in[15];
    const float* Wfc  = (const float*)d_in[16];
    const float* bfc  = (const float*)d_in[17];
    float* out = (float*)d_out;
    float* out_h1f = out + H1F_OFF;

    const int SMEM1 = (BPC_*SB_ + RPC_*WROW_ + BPC_*C_ + RPC_*C_ + RPC_ + RPC_ + 16*72) * 4;
    const int SMEM2A = (48*H1_ + 48 + 8*4*48) * 4;
    cudaFuncSetAttribute(gru1_t<true>,  cudaFuncAttributeMaxDynamicSharedMemorySize, SMEM1);
    cudaFuncSetAttribute(gru1_t<true>,  cudaFuncAttributeNonPortableClusterSizeAllowed, 1);
    cudaFuncSetAttribute(gru1_t<false>, cudaFuncAttributeMaxDynamicSharedMemorySize, SMEM1);
    cudaFuncSetAttribute(gru2a_kernel,  cudaFuncAttributeMaxDynamicSharedMemorySize, SMEM2A);

    // Try HW-cluster path (16-CTA clusters); fall back to software barrier.
    cudaLaunchConfig_t cfg = {};
    cfg.gridDim  = dim3(NBLK1, 1, 1);
    cfg.blockDim = dim3(512, 1, 1);
    cfg.dynamicSmemBytes = SMEM1;
    cfg.stream = 0;
    cudaLaunchAttribute at[1];
    at[0].id = cudaLaunchAttributeClusterDimension;
    at[0].val.clusterDim.x = CLUS_;
    at[0].val.clusterDim.y = 1;
    at[0].val.clusterDim.z = 1;
    cfg.attrs = at;
    cfg.numAttrs = 1;

    int nclus = 0;
    cudaError_t qe = cudaOccupancyMaxActiveClusters(&nclus, gru1_t<true>, &cfg);
    if (qe != cudaSuccess) { (void)cudaGetLastError(); nclus = 0; }

    if (nclus >= 1) {
        cudaLaunchKernelEx(&cfg, gru1_t<true>,
                           x, h1, Wih1, Whh1, bih1, bhh1, out_h1f);
    } else {
        gru1_t<false><<<NBLK1, 512, SMEM1>>>(
            x, h1, Wih1, Whh1, bih1, bhh1, out_h1f);
    }

    gru2a_kernel<<<256, 256, SMEM2A>>>(Wih2, bih2);
    gru2b_kernel<<<B_, 32>>>(h2, Whh2, bhh2, Wfc, bfc, out);
    gru3_kernel<<<B_, 32>>>(h3, Wih3, Whh3, bih3, bhh3, out);
}

// round 16
// speedup vs baseline: 1.3845x; 1.3845x over previous
#include <cuda_runtime.h>
#include <cstddef>

// Problem constants
#define B_  64
#define L_  2048
#define C_  20
#define H1_ 384
#define H2_ 16
#define F_  20

// Output layout (flattened tuple, reference order):
// x_mid (B,L,F) | x_out (B,L,F) | h1f (B,H1) | h2f (B,H2) | h3f (B,F)
#define XMID_OFF 0
#define XOUT_OFF (B_*L_*F_)
#define H1F_OFF  (2*B_*L_*F_)
#define H2F_OFF  (H1F_OFF + B_*H1_)
#define H3F_OFF  (H2F_OFF + B_*H2_)

// Scratch (device globals: allocation-free rule)
__device__ float g_h1[H1_*B_];                   // [unit][batch] layout!
__device__ float g_y1[(size_t)B_*L_*H1_];        // 201 MB
__device__ float g_xp[(size_t)B_*L_*48];         // 25 MB (gru2 input proj)
__device__ unsigned g_bar_cnt[8];                // per-batch-group arrivals
__device__ unsigned g_bar_gen[8];                // monotonic across launches

// GRU1 partition: 16 row-groups x 8 batch-groups = 128 CTAs (1 per SM).
// Each CTA: 24 hidden units (72 gate rows, SMEM-resident) x 8 batches.
// 512 threads = 16 warps = 8 rgrp x 2 khalf. Warp tile: 9 rows x 8 b x 192 k.
// Lane = (ko 0..7, bl 0..3): 9 rows x 2 batches x 24 k per lane, f32x2 FMA.
#define NBLK1 128
#define GRP_  16     // CTAs per batch group
#define UPC_  24     // units per CTA
#define RPC_  72     // gate rows per CTA (3*UPC)
#define BPC_  8      // batches per CTA
// SMEM strides (floats): k stored in 4 chunks of 96 (+4 pad)
#define SK_   100
#define SB_   420
#define WROW_ 420

__device__ __forceinline__ unsigned long long fma2_(
    unsigned long long a, unsigned long long b, unsigned long long c)
{
    unsigned long long d;
    asm("fma.rn.f32x2 %0, %1, %2, %3;" : "=l"(d) : "l"(a), "l"(b), "l"(c));
    return d;
}

// ---------------------------------------------------------------------------
// Kernel 1: GRU1 (C=20 -> H1=384), persistent, per-batch-group barrier
// with acquire/release semantics (no second fence, no volatile spin).
// ---------------------------------------------------------------------------
__global__ __launch_bounds__(512, 1) void gru1_kernel(
    const float* __restrict__ x, const float* __restrict__ h1_in,
    const float* __restrict__ Wih1, const float* __restrict__ Whh1,
    const float* __restrict__ bih1, const float* __restrict__ bhh1,
    float* __restrict__ out_h1f)
{
    extern __shared__ float sm[];
    float* h_s  = sm;                       // BPC*SB   = 3360
    float* Wh_s = h_s  + BPC_*SB_;          // RPC*WROW = 30240
    float* xs   = Wh_s + RPC_*WROW_;        // BPC*20   = 160
    float* Wi_s = xs   + BPC_*C_;           // RPC*20   = 1440
    float* bi_s = Wi_s + RPC_*C_;           // 72
    float* bh_s = bi_s + RPC_;              // 72
    float* red  = bh_s + RPC_;              // 16*72 = 1152

    const int tid  = threadIdx.x;
    const int lane = tid & 31;
    const int w    = tid >> 5;                 // 0..15
    const int rg   = blockIdx.x & (GRP_-1);    // row group 0..15
    const int bg   = blockIdx.x >> 4;          // batch group 0..7
    const int u0   = rg * UPC_;                // first global hidden unit
    const int b0c  = bg * BPC_;                // first global batch

    const int rgrp  = w >> 1;                  // 0..7 -> units rgrp*3..+2
    const int khalf = w & 1;                   // 0..1 -> k 0..191 / 192..383
    const int ko    = lane >> 2;               // k octet within half (24 k)
    const int bl    = lane & 3;                // batch pair base (bl, bl+4)

    // ---- load recurrent weights into SMEM (chunked-k layout) ----
    for (int i = tid; i < RPC_*H1_; i += 512) {
        int lr = i / H1_, k = i % H1_;
        int g = lr / UPC_, ul = lr % UPC_;
        Wh_s[lr*WROW_ + (k/96)*SK_ + (k%96)] =
            Whh1[(size_t)(g*H1_ + u0 + ul)*H1_ + k];
    }
    for (int i = tid; i < RPC_*C_; i += 512) {
        int lr = i / C_, c = i % C_;
        int g = lr / UPC_, ul = lr % UPC_;
        Wi_s[i] = Wih1[(g*H1_ + u0 + ul)*C_ + c];
    }
    if (tid < RPC_) {
        int g = tid / UPC_, ul = tid % UPC_;
        bi_s[tid] = bih1[g*H1_ + u0 + ul];
        bh_s[tid] = bhh1[g*H1_ + u0 + ul];
    }

    // barrier generation base (stable: previous launch fully done)
    const unsigned base = *(volatile unsigned*)&g_bar_gen[bg];

    // per-lane k base: global k = khalf*192 + ko*24 + [0..23]
    const int c0  = khalf*2 + (ko >> 2);       // 96-chunk index
    const int off = (ko & 3) * 24;
    const float* hb0 = h_s  + bl*SB_       + c0*SK_ + off;
    const float* hb1 = h_s  + (bl+4)*SB_   + c0*SK_ + off;
    const float* wb  = Wh_s + (rgrp*3)*WROW_ + c0*SK_ + off;

    // epilogue identity (t-invariant): even warps, 24 lanes = 3 units x 8 b
    const bool epi = (khalf == 0) && (lane < 24);
    const int  eu   = lane >> 3;               // 0..2
    const int  ebl  = lane & 7;
    const int  eb   = b0c + ebl;               // global batch
    const int  eul  = rgrp*3 + eu;             // local unit 0..23
    const int  eug  = u0 + eul;                // global hidden unit

    // ---- prologue: h(t=0) from h1_in ([b][u] layout) + x(0) ----
    {
        const float4* s4 = (const float4*)(h1_in + b0c*H1_);
        for (int i4 = tid; i4 < BPC_*(H1_/4); i4 += 512) {
            int b = i4 / 96, k4 = i4 % 96;
            float4 v = __ldg(s4 + i4);
            *((float4*)h_s + (size_t)b*(SB_/4) + (k4/24)*(SK_/4) + (k4%24)) = v;
        }
        if (tid < BPC_*5) {
            int b = tid / 5, c4 = tid % 5;
            ((float4*)(xs + b*C_))[c4] =
                __ldcg((const float4*)(x + ((size_t)(b0c + b)*L_)*C_) + c4);
        }
    }
    __syncthreads();

    for (int t = 0; t < L_; t++) {
        // ---- recurrent GEMM: 9 rows x 2 batches x 24 k per lane ----
        unsigned long long acc[18];
        #pragma unroll
        for (int r = 0; r < 18; r++) acc[r] = 0ull;

        #pragma unroll
        for (int j = 0; j < 6; j++) {
            const ulonglong2 ha = *(const ulonglong2*)(hb0 + 4*j);
            const ulonglong2 hc = *(const ulonglong2*)(hb1 + 4*j);
            #pragma unroll
            for (int g = 0; g < 3; g++) {
                #pragma unroll
                for (int u = 0; u < 3; u++) {
                    const ulonglong2 w2 =
                        *(const ulonglong2*)(wb + (g*UPC_ + u)*WROW_ + 4*j);
                    const int r = g*3 + u;
                    acc[r*2]   = fma2_(w2.x, ha.x, acc[r*2]);
                    acc[r*2]   = fma2_(w2.y, ha.y, acc[r*2]);
                    acc[r*2+1] = fma2_(w2.x, hc.x, acc[r*2+1]);
                    acc[r*2+1] = fma2_(w2.y, hc.y, acc[r*2+1]);
                }
            }
        }
        // unpack f32x2 partials, reduce over ko (lane bits 2..4)
        float s[18];
        #pragma unroll
        for (int r = 0; r < 18; r++) {
            float lo, hi;
            asm("mov.b64 {%0,%1}, %2;" : "=f"(lo), "=f"(hi) : "l"(acc[r]));
            s[r] = lo + hi;
        }
        #pragma unroll
        for (int r = 0; r < 18; r++) {
            s[r] += __shfl_xor_sync(0xffffffffu, s[r], 4);
            s[r] += __shfl_xor_sync(0xffffffffu, s[r], 8);
            s[r] += __shfl_xor_sync(0xffffffffu, s[r], 16);
        }
        if (ko == 0) {
            #pragma unroll
            for (int r = 0; r < 9; r++) {
                red[w*72 + r*8 + bl]     = s[r*2];
                red[w*72 + r*8 + bl + 4] = s[r*2+1];
            }
        }
        __syncthreads();   // cross-warp (khalf) combine

        // ---- epilogue: even warps, 24 lanes = 3 units x 8 batches ----
        float hn = 0.f;
        if (epi) {
            float xr = bi_s[eul], xz = bi_s[UPC_+eul], xn = bi_s[2*UPC_+eul];
            #pragma unroll
            for (int c = 0; c < C_; c++) {
                float xv = xs[ebl*C_ + c];
                xr = fmaf(Wi_s[eul*C_ + c],            xv, xr);
                xz = fmaf(Wi_s[(UPC_+eul)*C_ + c],     xv, xz);
                xn = fmaf(Wi_s[(2*UPC_+eul)*C_ + c],   xv, xn);
            }
            const int w0 = rgrp*2, w1 = rgrp*2 + 1;
            float ghr = red[w0*72 + (eu  )*8 + ebl] + red[w1*72 + (eu  )*8 + ebl] + bh_s[eul];
            float ghz = red[w0*72 + (3+eu)*8 + ebl] + red[w1*72 + (3+eu)*8 + ebl] + bh_s[UPC_+eul];
            float ghn = red[w0*72 + (6+eu)*8 + ebl] + red[w1*72 + (6+eu)*8 + ebl] + bh_s[2*UPC_+eul];
            float rgt = 1.f / (1.f + __expf(-(xr + ghr)));
            float zgt = 1.f / (1.f + __expf(-(xz + ghz)));
            float ngt = tanhf(xn + rgt * ghn);
            float hold = h_s[ebl*SB_ + (eug/96)*SK_ + (eug%96)];
            hn = (1.f - zgt) * ngt + zgt * hold;
            // coalesced store: [unit][batch] layout (3 x 32B per warp)
            __stcg(&g_h1[eug*B_ + eb], hn);
            __threadfence();               // publish h before arrival
        }
        __syncthreads();                   // all epi stores fenced

        const bool last = (t == L_-1);

        // ---- arrival (release) ----
        if (!last && tid == 0) {
            unsigned old;
            asm volatile("atom.acq_rel.gpu.global.add.u32 %0, [%1], %2;"
                         : "=r"(old) : "l"(&g_bar_cnt[bg]), "r"(1u) : "memory");
            if (old == GRP_ - 1) {
                g_bar_cnt[bg] = 0;
                asm volatile("st.release.gpu.global.u32 [%0], %1;"
                             :: "l"(&g_bar_gen[bg]), "r"(base + (unsigned)(t+1))
                             : "memory");
            }
        }

        // ---- wait-window work: y1 store + next x load ----
        if (epi) {
            g_y1[((size_t)eb*L_ + t)*H1_ + eug] = hn;
            if (last) out_h1f[eb*H1_ + eug] = hn;
        }
        if (last) break;

        if (tid < BPC_*5) {
            int b = tid / 5, c4 = tid % 5;
            ((float4*)(xs + b*C_))[c4] =
                __ldcg((const float4*)(x + ((size_t)(b0c + b)*L_ + (t+1))*C_) + c4);
        }

        // ---- poll (acquire) ----
        if (tid == 0) {
            unsigned v;
            for (;;) {
                asm volatile("ld.acquire.gpu.global.u32 %0, [%1];"
                             : "=r"(v) : "l"(&g_bar_gen[bg]) : "memory");
                if (v - base >= (unsigned)(t+1)) break;
                __nanosleep(16);
            }
        }
        __syncthreads();

        // ---- load h(t+1) from g_h1 [u][b]: 32B per unit, transpose to SMEM ----
        #pragma unroll 1
        for (int j = tid; j < H1_*2; j += 512) {
            const int u = j >> 1, half = j & 1;
            float4 v = __ldcg((const float4*)(g_h1 + u*B_ + b0c) + half);
            float* dst = h_s + (half*4)*SB_ + (u/96)*SK_ + (u%96);
            dst[0]      = v.x;
            dst[SB_]    = v.y;
            dst[2*SB_]  = v.z;
            dst[3*SB_]  = v.w;
        }
        __syncthreads();
    }
}

// ---------------------------------------------------------------------------
// Kernel 2a: gru2 input projection xp = y1 @ Wih2^T + bih2  (time-parallel).
// ---------------------------------------------------------------------------
__global__ __launch_bounds__(256) void gru2a_kernel(
    const float* __restrict__ Wih2, const float* __restrict__ bih2)
{
    extern __shared__ float sm[];
    float* W2s = sm;                 // 48*384 = 18432
    float* bis = W2s + 48*H1_;       // 48
    float* xps = bis + 48;           // 8 warps * 4 rows * 48 = 1536

    const int tid = threadIdx.x, lane = tid & 31, w = tid >> 5;

    for (int i = tid; i < 48*H1_; i += 256) W2s[i] = Wih2[i];
    if (tid < 48) bis[tid] = bih2[tid];
    __syncthreads();

    const int nquad = (B_*L_) / 4;                 // 32768
    const int gw    = blockIdx.x*8 + w;            // global warp id
    const int nw    = gridDim.x*8;

    for (int q = gw; q < nquad; q += nw) {
        const int row0 = q * 4;
        float4 y[4][3];
        #pragma unroll
        for (int r = 0; r < 4; r++) {
            const float4* yr = (const float4*)(g_y1 + (size_t)(row0 + r)*H1_);
            y[r][0] = __ldg(yr + lane);
            y[r][1] = __ldg(yr + 32 + lane);
            y[r][2] = __ldg(yr + 64 + lane);
        }
        for (int g = 0; g < 48; g++) {
            const float* wr = W2s + g*H1_;
            const float4 w0 = *(const float4*)(wr + 4*lane);
            const float4 w1 = *(const float4*)(wr + 128 + 4*lane);
            const float4 w2 = *(const float4*)(wr + 256 + 4*lane);
            #pragma unroll
            for (int r = 0; r < 4; r++) {
                float s = w0.x*y[r][0].x + w0.y*y[r][0].y
                        + w0.z*y[r][0].z + w0.w*y[r][0].w;
                s = fmaf(w1.x, y[r][1].x, s); s = fmaf(w1.y, y[r][1].y, s);
                s = fmaf(w1.z, y[r][1].z, s); s = fmaf(w1.w, y[r][1].w, s);
                s = fmaf(w2.x, y[r][2].x, s); s = fmaf(w2.y, y[r][2].y, s);
                s = fmaf(w2.z, y[r][2].z, s); s = fmaf(w2.w, y[r][2].w, s);
                #pragma unroll
                for (int d = 16; d > 0; d >>= 1)
                    s += __shfl_xor_sync(0xffffffffu, s, d);
                if (lane == (g & 31)) xps[(w*4 + r)*48 + g] = s + bis[g];
            }
        }
        __syncwarp();
        #pragma unroll
        for (int r = 0; r < 4; r++)
            if (lane < 12)
                ((float4*)&g_xp[(size_t)(row0 + r)*48])[lane] =
                    ((float4*)&xps[(w*4 + r)*48])[lane];
        __syncwarp();
    }
}

// ---------------------------------------------------------------------------
// Kernel 2b: gru2 recurrence (H2=16) + ReLU + dual-FC -> x_mid.
// One warp per batch; h in registers; shuffle broadcasts; xp ring prefetch.
// ---------------------------------------------------------------------------
__global__ __launch_bounds__(32) void gru2b_kernel(
    const float* __restrict__ h2_in,
    const float* __restrict__ Whh2, const float* __restrict__ bhh2,
    const float* __restrict__ Wfc,  const float* __restrict__ bfc,
    float* __restrict__ out)
{
    __shared__ float Wh[48*16], Wf[20*16], bh[48], bf[20];
    __shared__ __align__(16) float ring[4][48];

    const int lane = threadIdx.x;
    const int b = blockIdx.x;
    const int r0 = lane & 15;
    const int fr = (lane < 20) ? lane : 0;

    for (int i = lane; i < 48*16; i += 32) Wh[i] = Whh2[i];
    for (int i = lane; i < 20*16; i += 32) Wf[i] = Wfc[i];
    for (int i = lane; i < 48;    i += 32) bh[i] = bhh2[i];
    if (lane < 20) bf[lane] = bfc[lane];

    float h = (lane < 16) ? h2_in[b*H2_ + lane] : 0.f;

    const float* xpb = g_xp + (size_t)b*L_*48;
    if (lane < 24) {   // prime rows 0,1
        int r = lane / 12, c = lane % 12;
        ((float4*)ring[r])[c] = __ldg((const float4*)(xpb + r*48) + c);
    }
    __syncwarp();

    for (int t = 0; t < L_; t++) {
        float4 pf;
        const bool dp = (lane < 12) && (t + 2 < L_);
        if (dp) pf = __ldg((const float4*)(xpb + (size_t)(t + 2)*48) + lane);

        const float* cur = ring[t & 3];

        float ghr = bh[r0], ghz = bh[16 + r0], ghn = bh[32 + r0];
        #pragma unroll
        for (int k = 0; k < 16; k++) {
            float hv = __shfl_sync(0xffffffffu, h, k);
            ghr = fmaf(Wh[r0*16 + k],        hv, ghr);
            ghz = fmaf(Wh[(16+r0)*16 + k],   hv, ghz);
            ghn = fmaf(Wh[(32+r0)*16 + k],   hv, ghn);
        }
        float rg = 1.f / (1.f + __expf(-(cur[r0]      + ghr)));
        float zg = 1.f / (1.f + __expf(-(cur[16 + r0] + ghz)));
        float ng = tanhf(cur[32 + r0] + rg * ghn);
        float hn = (1.f - zg) * ng + zg * h;
        if (lane < 16) h = hn;
        float y2 = fmaxf(hn, 0.f);

        float a = bf[fr];
        #pragma unroll
        for (int k = 0; k < 16; k++) {
            float yv = __shfl_sync(0xffffffffu, y2, k);
            a = fmaf(Wf[fr*16 + k], yv, a);
        }
        if (lane < 20)
            out[XMID_OFF + ((size_t)b*L_ + t)*F_ + lane] = 2.f * tanhf(a);

        if (dp) ((float4*)ring[(t + 2) & 3])[lane] = pf;
        __syncwarp();
    }
    if (lane < 16) out[H2F_OFF + b*H2_ + lane] = h;
}

// ---------------------------------------------------------------------------
// Kernel 3: GRU3 (F=20 -> F=20) on time-reversed x_mid, x_out = tanh(y3).
// One warp per batch element.
// ---------------------------------------------------------------------------
__global__ __launch_bounds__(32) void gru3_kernel(
    const float* __restrict__ h3_in,
    const float* __restrict__ Wih3, const float* __restrict__ Whh3,
    const float* __restrict__ bih3, const float* __restrict__ bhh3,
    float* __restrict__ out)
{
    __shared__ float Wi[60*20], Wh[60*20];
    __shared__ float bi[60], bh[60], as_[60], gs_[60], h3s[20];
    __shared__ __align__(16) float ins[2][20];

    const int lane = threadIdx.x;
    const int b = blockIdx.x;

    for (int i = lane; i < 60*20; i += 32) { Wi[i] = Wih3[i]; Wh[i] = Whh3[i]; }
    for (int i = lane; i < 60;    i += 32) { bi[i] = bih3[i]; bh[i] = bhh3[i]; }
    if (lane < 20) h3s[lane] = h3_in[b*F_ + lane];

    const float* xmid = out + XMID_OFF + (size_t)b*L_*F_;
    if (lane < 5)
        ((float4*)ins[0])[lane] = *((const float4*)(xmid + (size_t)(L_-1)*F_) + lane);
    __syncwarp();

    for (int t = 0; t < L_; t++) {
        float* in = ins[t & 1];
        float4 pf;
        bool dopf = (lane < 5) && (t + 1 < L_);
        if (dopf)
            pf = *((const float4*)(xmid + (size_t)(L_-2-t)*F_) + lane);

        const int r1 = lane + 32;
        const bool has1 = (r1 < 60);
        float a0 = bi[lane], g0 = bh[lane], a1 = 0.f, g1 = 0.f;
        if (has1) { a1 = bi[r1]; g1 = bh[r1]; }
        #pragma unroll
        for (int k = 0; k < 20; k++) {
            float iv = in[k], hv = h3s[k];
            a0 = fmaf(Wi[lane*20 + k], iv, a0);
            g0 = fmaf(Wh[lane*20 + k], hv, g0);
            if (has1) {
                a1 = fmaf(Wi[r1*20 + k], iv, a1);
                g1 = fmaf(Wh[r1*20 + k], hv, g1);
            }
        }
        as_[lane] = a0; gs_[lane] = g0;
        if (has1) { as_[r1] = a1; gs_[r1] = g1; }
        __syncwarp();

        float hn = 0.f;
        if (lane < 20) {
            float rg = 1.f / (1.f + __expf(-(as_[lane] + gs_[lane])));
            float zg = 1.f / (1.f + __expf(-(as_[20+lane] + gs_[20+lane])));
            float ng = tanhf(as_[40+lane] + rg * gs_[40+lane]);
            hn = (1.f - zg) * ng + zg * h3s[lane];
        }
        __syncwarp();
        if (lane < 20) {
            h3s[lane] = hn;
            out[XOUT_OFF + ((size_t)b*L_ + t)*F_ + lane] = tanhf(hn);
        }
        if (dopf) ((float4*)ins[(t + 1) & 1])[lane] = pf;
        __syncwarp();
    }
    if (lane < 20) out[H3F_OFF + b*F_ + lane] = h3s[lane];
}

// ---------------------------------------------------------------------------
extern "C" void kernel_launch(void* const* d_in, const int* in_sizes, int n_in,
                              void* d_out, int out_size)
{
    const float* x    = (const float*)d_in[0];
    const float* h1   = (const float*)d_in[1];
    const float* h2   = (const float*)d_in[2];
    const float* h3   = (const float*)d_in[3];
    const float* Wih1 = (const float*)d_in[4];
    const float* Whh1 = (const float*)d_in[5];
    const float* bih1 = (const float*)d_in[6];
    const float* bhh1 = (const float*)d_in[7];
    const float* Wih2 = (const float*)d_in[8];
    const float* Whh2 = (const float*)d_in[9];
    const float* bih2 = (const float*)d_in[10];
    const float* bhh2 = (const float*)d_in[11];
    const float* Wih3 = (const float*)d_in[12];
    const float* Whh3 = (const float*)d_in[13];
    const float* bih3 = (const float*)d_in[14];
    const float* bhh3 = (const float*)d_in[15];
    const float* Wfc  = (const float*)d_in[16];
    const float* bfc  = (const float*)d_in[17];
    float* out = (float*)d_out;

    const int SMEM1 = (BPC_*SB_ + RPC_*WROW_ + BPC_*C_ + RPC_*C_ + RPC_ + RPC_ + 16*72) * 4;
    const int SMEM2A = (48*H1_ + 48 + 8*4*48) * 4;
    cudaFuncSetAttribute(gru1_kernel,  cudaFuncAttributeMaxDynamicSharedMemorySize, SMEM1);
    cudaFuncSetAttribute(gru2a_kernel, cudaFuncAttributeMaxDynamicSharedMemorySize, SMEM2A);

    gru1_kernel<<<NBLK1, 512, SMEM1>>>(x, h1, Wih1, Whh1, bih1, bhh1, out + H1F_OFF);
    gru2a_kernel<<<256, 256, SMEM2A>>>(Wih2, bih2);
    gru2b_kernel<<<B_, 32>>>(h2, Whh2, bhh2, Wfc, bfc, out);
    gru3_kernel<<<B_, 32>>>(h3, Wih3, Whh3, bih3, bhh3, out);
}